// round 9
// baseline (speedup 1.0000x reference)
#include <cuda_runtime.h>
#include <cuda_bf16.h>
#include <math.h>
#include <stdint.h>

// Problem constants
#define BATCH 2048      // B*T
#define NAG   16
#define NACT  20
#define DDIM  128
#define NSAMP 32
#define EDIM  64
#define HDIM  256
#define W1N   2560      // E*2*A
#define CATN  640       // 256(h1a)+256(hf)+64(b1)+64(vh)

// ---------------- scratch (device globals) ----------------
__device__ float g_out0[BATCH * CATN];
__device__ __nv_bfloat16 g_Ahi[BATCH * HDIM];
__device__ __nv_bfloat16 g_Alo[BATCH * HDIM];
__device__ __nv_bfloat16 g_Bhi[W1N * HDIM];
__device__ __nv_bfloat16 g_Blo[W1N * HDIM];
__device__ float g_w1 [BATCH * W1N];
__device__ float g_wf [BATCH * EDIM];
__device__ float g_coal[BATCH * NAG * NACT];

// ===================== PTX helpers =====================
__device__ __forceinline__ uint32_t smem_to_u32(const void* p) {
    uint32_t a;
    asm("{ .reg .u64 t; cvta.to.shared.u64 t, %1; cvt.u32.u64 %0, t; }" : "=r"(a) : "l"(p));
    return a;
}
#define LDMATRIX_X4(r, a) \
    asm volatile("ldmatrix.sync.aligned.m8n8.x4.shared.b16 {%0,%1,%2,%3}, [%4];" \
        : "=r"((r)[0]), "=r"((r)[1]), "=r"((r)[2]), "=r"((r)[3]) : "r"(a))
#define MMA16816(c, a, b0, b1) \
    asm volatile("mma.sync.aligned.m16n8k16.row.col.f32.bf16.bf16.f32 " \
        "{%0,%1,%2,%3},{%4,%5,%6,%7},{%8,%9},{%0,%1,%2,%3};" \
        : "+f"((c)[0]), "+f"((c)[1]), "+f"((c)[2]), "+f"((c)[3]) \
        : "r"((a)[0]), "r"((a)[1]), "r"((a)[2]), "r"((a)[3]), "r"(b0), "r"(b1))
#define CP_ASYNC16(dst, src) \
    asm volatile("cp.async.cg.shared.global [%0], [%1], 16;" :: "r"(dst), "l"(src))
#define CP_COMMIT() asm volatile("cp.async.commit_group;" ::: "memory")
#define CP_WAIT1()  asm volatile("cp.async.wait_group 1;" ::: "memory")
#define CP_WAIT0()  asm volatile("cp.async.wait_group 0;" ::: "memory")

// ======================================================================
// STAGE 1: gemm0 (320) + trans_split (640) + coal (256 x 8-batch)
// ======================================================================
#define S1_GEMM0_BLKS 320
#define S1_TRANS_BLKS 640
#define S1_COAL_BLKS  256
#define S1_TOTAL (S1_GEMM0_BLKS + S1_TRANS_BLKS + S1_COAL_BLKS)
#define SMEM_S1  66560   // As 64x132 (33792 B) + Bs 128x64 (32768 B)

// ---- gemm0: states[2048x128] @ [W1a|Wfa|Wb|Wv1], 64x64 tile, single sync ----
__device__ __forceinline__ void gemm0_block(
    int bx, char* smraw, const float* __restrict__ states,
    const float* __restrict__ W1a, const float* __restrict__ b1a,
    const float* __restrict__ Wfa, const float* __restrict__ bfa,
    const float* __restrict__ Wb,  const float* __restrict__ bb,
    const float* __restrict__ Wv1, const float* __restrict__ bv1)
{
    float* As = (float*)smraw;                   // [64][132] (m,k)
    float* Bs = (float*)(smraw + 33792);         // [128][64] (k,n)

    const int tid = threadIdx.x;
    const int n0 = (bx % 10) * 64;
    const int m0 = (bx / 10) * 64;
    const int tx = tid & 15, ty = tid >> 4;

    const float* Bsrc; const float* bias; int ldb; int nc0;
    if      (n0 < 256) { Bsrc = W1a; bias = b1a; ldb = 256; nc0 = n0; }
    else if (n0 < 512) { Bsrc = Wfa; bias = bfa; ldb = 256; nc0 = n0 - 256; }
    else if (n0 < 576) { Bsrc = Wb;  bias = bb;  ldb = 64;  nc0 = 0; }
    else               { Bsrc = Wv1; bias = bv1; ldb = 64;  nc0 = 0; }

#pragma unroll
    for (int j = 0; j < 8; j++) {
        int idx = tid + j * 256;
        int k = idx >> 4, c = idx & 15;
        CP_ASYNC16(smem_to_u32(&Bs[k * 64 + c * 4]),
                   Bsrc + (size_t)k * ldb + nc0 + c * 4);
    }
    CP_COMMIT();

#pragma unroll
    for (int j = 0; j < 8; j++) {
        int idx = tid + j * 256;
        int kg = idx & 31, m = idx >> 5;
        float4 v = *(const float4*)(states + (size_t)(m0 + m) * DDIM + kg * 4);
        *(float4*)&As[m * 132 + kg * 4] = v;
    }
    CP_WAIT0();
    __syncthreads();

    float acc[4][4];
#pragma unroll
    for (int r = 0; r < 4; r++)
#pragma unroll
        for (int j = 0; j < 4; j++) acc[r][j] = 0.f;

#pragma unroll 8
    for (int kk = 0; kk < 128; kk++) {
        float av[4];
#pragma unroll
        for (int r = 0; r < 4; r++) av[r] = As[(ty * 4 + r) * 132 + kk];
        float4 bv = *(const float4*)&Bs[kk * 64 + tx * 4];
        float bw[4] = {bv.x, bv.y, bv.z, bv.w};
#pragma unroll
        for (int r = 0; r < 4; r++)
#pragma unroll
            for (int j = 0; j < 4; j++)
                acc[r][j] += av[r] * bw[j];
    }

    const bool do_relu = (n0 != 512);
    float bs[4];
#pragma unroll
    for (int j = 0; j < 4; j++) bs[j] = bias[nc0 + tx * 4 + j];

#pragma unroll
    for (int r = 0; r < 4; r++) {
        int m = m0 + ty * 4 + r;
        float4 o;
        float* po = &o.x;
#pragma unroll
        for (int j = 0; j < 4; j++) {
            float v = acc[r][j] + bs[j];
            if (do_relu) v = fmaxf(v, 0.f);
            po[j] = v;
        }
        *(float4*)&g_out0[(size_t)m * CATN + n0 + tx * 4] = o;
        if (n0 < 256) {
            __nv_bfloat16 h[4]; float lo[4];
#pragma unroll
            for (int j = 0; j < 4; j++) {
                h[j] = __float2bfloat16(po[j]);
                lo[j] = po[j] - __bfloat162float(h[j]);
            }
            size_t base = (size_t)m * HDIM + n0 + tx * 4;
            *(__nv_bfloat162*)&g_Ahi[base]     = __nv_bfloat162(h[0], h[1]);
            *(__nv_bfloat162*)&g_Ahi[base + 2] = __nv_bfloat162(h[2], h[3]);
            *(__nv_bfloat162*)&g_Alo[base]     = __nv_bfloat162(__float2bfloat16(lo[0]), __float2bfloat16(lo[1]));
            *(__nv_bfloat162*)&g_Alo[base + 2] = __nv_bfloat162(__float2bfloat16(lo[2]), __float2bfloat16(lo[3]));
        }
    }
}

// ---- trans_split ----
__device__ __forceinline__ void trans_block(int t, char* smraw, const float* __restrict__ W1b)
{
    float* ts = (float*)smraw;      // [32][33]
    int n0 = (t % 80) * 32, k0 = (t / 80) * 32;
    int tx = threadIdx.x & 31, ty = threadIdx.x >> 5;
#pragma unroll
    for (int r = 0; r < 4; r++)
        ts[(ty * 4 + r) * 33 + tx] = W1b[(size_t)(k0 + ty * 4 + r) * W1N + n0 + tx];
    __syncthreads();
#pragma unroll
    for (int r = 0; r < 4; r++) {
        int n = n0 + ty * 4 + r, k = k0 + tx;
        float v = ts[tx * 33 + ty * 4 + r];
        __nv_bfloat16 hi = __float2bfloat16(v);
        float lof = v - __bfloat162float(hi);
        g_Bhi[(size_t)n * HDIM + k] = hi;
        g_Blo[(size_t)n * HDIM + k] = __float2bfloat16(lof);
    }
}

// ---- coal: 8 batches per block ----
__device__ __forceinline__ void coal_multi(int cb, char* smraw,
    const float* __restrict__ actions, const int* __restrict__ gc)
{
    int*   gcs   = (int*)smraw;              // [32][16]
    int*   inv   = gcs + 512;                // [32][16]
    float* act_s = (float*)(inv + 512);      // [16][20]
    float* Ws    = act_s + 320;              // [16][16]

    const int tid = threadIdx.x;

    for (int bi = 0; bi < 8; bi++) {
        const int b = cb * 8 + bi;
        for (int idx = tid; idx < 512; idx += 256)
            gcs[idx] = gc[b * 512 + idx];
        for (int idx = tid; idx < 320; idx += 256)
            act_s[idx] = actions[b * 320 + idx];
        __syncthreads();

        {
            int s = tid >> 4, pos = tid & 15;
            inv[s * 16 + gcs[s * 16 + pos]] = pos;
            inv[(s + 16) * 16 + gcs[(s + 16) * 16 + pos]] = pos;
        }
        __syncthreads();

        {
            int i = tid >> 4, m = tid & 15;
            int w = 0;
#pragma unroll
            for (int s = 0; s < 32; s++) {
                int gi = gcs[s * 16 + i];
                int pm = inv[s * 16 + m];
                w += (pm < gi) ? gi : 0;
            }
            Ws[i * 16 + m] = (float)w;
        }
        __syncthreads();

        {
            int i = tid >> 4, c = tid & 15;
            for (int a = c; a < NACT; a += 16) {
                float sum = 0.f;
#pragma unroll
                for (int m = 0; m < 16; m++)
                    sum += Ws[i * 16 + m] * act_s[m * NACT + a];
                g_coal[b * 320 + i * NACT + a] = sum * (1.f / 512.f);
            }
        }
        __syncthreads();   // before smem reuse next batch
    }
}

__global__ void __launch_bounds__(256)
stage1_kernel(const float* __restrict__ states,
              const float* __restrict__ W1a, const float* __restrict__ b1a,
              const float* __restrict__ Wfa, const float* __restrict__ bfa,
              const float* __restrict__ Wb,  const float* __restrict__ bb,
              const float* __restrict__ Wv1, const float* __restrict__ bv1,
              const float* __restrict__ W1b,
              const float* __restrict__ actions, const int* __restrict__ gc)
{
    extern __shared__ __align__(16) char smd[];
    const int bx = blockIdx.x;
    if (bx < S1_GEMM0_BLKS)
        gemm0_block(bx, smd, states, W1a, b1a, Wfa, bfa, Wb, bb, Wv1, bv1);
    else if (bx < S1_GEMM0_BLKS + S1_TRANS_BLKS)
        trans_block(bx - S1_GEMM0_BLKS, smd, W1b);
    else
        coal_multi(bx - S1_GEMM0_BLKS - S1_TRANS_BLKS, smd, actions, gc);
}

// ======================================================================
// STAGE 2: wf (128, first) + hmma 128x64 tiles (640 blocks)
// ======================================================================
#define T_ROWB    80
#define A_TBYTES  (128 * T_ROWB)   // 10240
#define B_TBYTES  (64 * T_ROWB)    // 5120
#define STAGE_B2  (2 * A_TBYTES + 2 * B_TBYTES)  // 30720
#define SMEM_S2   (2 * STAGE_B2)   // 61440

__device__ __forceinline__ void hmma_block(int bx, char* sm, const float* __restrict__ b1b)
{
    const int tid = threadIdx.x;
    const int wid = tid >> 5, lane = tid & 31;
    const int n0 = (bx % 40) * 64;
    const int m0 = (bx / 40) * 128;
    const int wm = (wid >> 1) * 32;    // 4 row groups of 32
    const int wn = (wid & 1) * 32;     // 2 col groups of 32

    float acc[2][4][4];
#pragma unroll
    for (int r = 0; r < 2; r++)
#pragma unroll
        for (int g = 0; g < 4; g++)
#pragma unroll
            for (int c = 0; c < 4; c++) acc[r][g][c] = 0.f;

    auto load_stage = [&](int s, int k0) {
        char* base = sm + s * STAGE_B2;
        // A hi/lo: 128 rows x 4 chunks = 512 each -> 2/thread
#pragma unroll
        for (int j = 0; j < 2; j++) {
            int idx = tid + j * 256;
            int row = idx >> 2, c = idx & 3;
            CP_ASYNC16(smem_to_u32(base + row * T_ROWB + c * 16),
                       (const char*)(g_Ahi + (size_t)(m0 + row) * HDIM + k0) + c * 16);
            CP_ASYNC16(smem_to_u32(base + A_TBYTES + row * T_ROWB + c * 16),
                       (const char*)(g_Alo + (size_t)(m0 + row) * HDIM + k0) + c * 16);
        }
        // B hi/lo: 64 rows x 4 chunks = 256 each -> 1/thread
        {
            int row = tid >> 2, c = tid & 3;
            CP_ASYNC16(smem_to_u32(base + 2 * A_TBYTES + row * T_ROWB + c * 16),
                       (const char*)(g_Bhi + (size_t)(n0 + row) * HDIM + k0) + c * 16);
            CP_ASYNC16(smem_to_u32(base + 2 * A_TBYTES + B_TBYTES + row * T_ROWB + c * 16),
                       (const char*)(g_Blo + (size_t)(n0 + row) * HDIM + k0) + c * 16);
        }
    };

    load_stage(0, 0);
    CP_COMMIT();

    for (int kc = 0; kc < 8; kc++) {
        if (kc < 7) { load_stage((kc + 1) & 1, (kc + 1) * 32); CP_COMMIT(); CP_WAIT1(); }
        else        { CP_WAIT0(); }
        __syncthreads();

        char* Ah = sm + (kc & 1) * STAGE_B2;
        char* Al = Ah + A_TBYTES;
        char* Bh = Ah + 2 * A_TBYTES;
        char* Bl = Bh + B_TBYTES;

#pragma unroll
        for (int ks = 0; ks < 2; ks++) {
            const int kb = ks * 32;
            uint32_t ah[2][4], al[2][4], bh[2][4], bl[2][4];
            const int arow = wm + (lane & 15);
            const int akb  = kb + (lane >> 4) * 16;
#pragma unroll
            for (int r = 0; r < 2; r++) {
                LDMATRIX_X4(ah[r], smem_to_u32(Ah + (arow + r * 16) * T_ROWB + akb));
                LDMATRIX_X4(al[r], smem_to_u32(Al + (arow + r * 16) * T_ROWB + akb));
            }
            const int brow = wn + (lane & 7) + (lane >> 4) * 8;
            const int bkb  = kb + ((lane >> 3) & 1) * 16;
#pragma unroll
            for (int g = 0; g < 2; g++) {
                LDMATRIX_X4(bh[g], smem_to_u32(Bh + (brow + g * 16) * T_ROWB + bkb));
                LDMATRIX_X4(bl[g], smem_to_u32(Bl + (brow + g * 16) * T_ROWB + bkb));
            }
#pragma unroll
            for (int r = 0; r < 2; r++)
#pragma unroll
                for (int g = 0; g < 4; g++) {
                    uint32_t b0h = bh[g >> 1][(g & 1) * 2], b1h = bh[g >> 1][(g & 1) * 2 + 1];
                    uint32_t b0l = bl[g >> 1][(g & 1) * 2], b1l = bl[g >> 1][(g & 1) * 2 + 1];
                    MMA16816(acc[r][g], ah[r], b0h, b1h);
                    MMA16816(acc[r][g], ah[r], b0l, b1l);
                    MMA16816(acc[r][g], al[r], b0h, b1h);
                }
        }
        __syncthreads();
    }

    const int mrow  = m0 + wm + (lane >> 2);
    const int ncol0 = n0 + wn + (lane & 3) * 2;
#pragma unroll
    for (int g = 0; g < 4; g++) {
        const int n = ncol0 + g * 8;
        float2 bias = *(const float2*)&b1b[n];
#pragma unroll
        for (int r = 0; r < 2; r++) {
            const int m = mrow + r * 16;
            float2 o0, o1;
            o0.x = fabsf(acc[r][g][0] + bias.x);
            o0.y = fabsf(acc[r][g][1] + bias.y);
            o1.x = fabsf(acc[r][g][2] + bias.x);
            o1.y = fabsf(acc[r][g][3] + bias.y);
            *(float2*)&g_w1[(size_t)m * W1N + n]       = o0;
            *(float2*)&g_w1[(size_t)(m + 8) * W1N + n] = o1;
        }
    }
}

__device__ __forceinline__ void wf_block(int wb, char* sm,
    const float* __restrict__ Wfb, const float* __restrict__ bfb)
{
    float* As = (float*)sm;             // [2][16][36]
    float* Bs = (float*)(sm + 4608);    // [2][32][64]
    const int tid = threadIdx.x;
    const int m0 = wb * 16;
    const int tx = tid & 15, ty = tid >> 4;

    auto load_stage = [&](int s, int k0) {
        if (tid < 128) {
            int row = tid >> 3, c = tid & 7;
            CP_ASYNC16(smem_to_u32(&As[s * 576 + row * 36 + c * 4]),
                       g_out0 + (size_t)(m0 + row) * CATN + 256 + k0 + c * 4);
        }
#pragma unroll
        for (int j = 0; j < 2; j++) {
            int idx = tid * 2 + j;
            int k = idx >> 4, c = idx & 15;
            CP_ASYNC16(smem_to_u32(&Bs[s * 2048 + k * 64 + c * 4]),
                       Wfb + (size_t)(k0 + k) * EDIM + c * 4);
        }
    };

    float acc[4] = {0.f, 0.f, 0.f, 0.f};
    load_stage(0, 0);
    CP_COMMIT();

    for (int c = 0; c < 8; c++) {
        if (c < 7) { load_stage((c + 1) & 1, (c + 1) * 32); CP_COMMIT(); CP_WAIT1(); }
        else       { CP_WAIT0(); }
        __syncthreads();
        const int buf = c & 1;
#pragma unroll
        for (int kk = 0; kk < 32; kk++) {
            float a = As[buf * 576 + ty * 36 + kk];
            float4 bv = *(const float4*)&Bs[buf * 2048 + kk * 64 + tx * 4];
            acc[0] += a * bv.x; acc[1] += a * bv.y;
            acc[2] += a * bv.z; acc[3] += a * bv.w;
        }
        __syncthreads();
    }

    float4 bsv = *(const float4*)&bfb[tx * 4];
    float4 o;
    o.x = fabsf(acc[0] + bsv.x);
    o.y = fabsf(acc[1] + bsv.y);
    o.z = fabsf(acc[2] + bsv.z);
    o.w = fabsf(acc[3] + bsv.w);
    *(float4*)&g_wf[(size_t)(m0 + ty) * EDIM + tx * 4] = o;
}

__global__ void __launch_bounds__(256)
stage2_kernel(const float* __restrict__ b1b,
              const float* __restrict__ Wfb, const float* __restrict__ bfb)
{
    extern __shared__ char sm[];
    const int bx = blockIdx.x;
    if (bx < 128) wf_block(bx, sm, Wfb, bfb);
    else          hmma_block(bx - 128, sm, b1b);
}

// ======================================================================
// STAGE 3: lean final mix (v fused), 256 threads
// ======================================================================
__global__ void __launch_bounds__(256)
final_kernel(const float* __restrict__ actions, const float* __restrict__ Wv2,
             const float* __restrict__ bv2, const float* __restrict__ agent_qs,
             float* __restrict__ q_out, float* __restrict__ w_out)
{
    const int b = blockIdx.x;
    const int tid = threadIdx.x;
    const int i = tid >> 4, c = tid & 15;

    __shared__ float w1s[W1N];
    __shared__ float ins[NAG][40];
    __shared__ float wfs[EDIM], b1s[EDIM];
    __shared__ float vtmp[EDIM];
    __shared__ float vredS;
    __shared__ float qpart[NAG];

    for (int idx = tid; idx < 640; idx += 256)
        ((float4*)w1s)[idx] = ((const float4*)(g_w1 + (size_t)b * W1N))[idx];
    for (int idx = tid; idx < 320; idx += 256) {
        ins[idx / NACT][idx % NACT]        = g_coal[b * 320 + idx];
        ins[idx / NACT][NACT + idx % NACT] = actions[b * 320 + idx];
    }
    if (tid < 64) {
        wfs[tid]  = g_wf[(size_t)b * EDIM + tid];
        b1s[tid]  = g_out0[(size_t)b * CATN + 512 + tid];
        vtmp[tid] = g_out0[(size_t)b * CATN + 576 + tid] * Wv2[tid];
    }
    __syncthreads();

    if (tid < 32) {
        float pv = vtmp[tid] + vtmp[tid + 32];
#pragma unroll
        for (int o = 16; o > 0; o >>= 1)
            pv += __shfl_down_sync(0xffffffffu, pv, o);
        if (tid == 0) vredS = pv + bv2[0];
    }
    __syncthreads();

    const int e0 = c * 4;
    float4 hb = *(const float4*)&b1s[e0];
    float h[4] = {hb.x, hb.y, hb.z, hb.w};
#pragma unroll
    for (int k = 0; k < 40; k++) {
        float a_ = ins[i][k];
        float4 w = *(const float4*)&w1s[k * EDIM + e0];
        h[0] += a_ * w.x; h[1] += a_ * w.y;
        h[2] += a_ * w.z; h[3] += a_ * w.w;
    }
    float4 wfv = *(const float4*)&wfs[e0];
    float pr;
    {
        float hd0 = h[0] > 0.f ? h[0] : expm1f(h[0]);
        float hd1 = h[1] > 0.f ? h[1] : expm1f(h[1]);
        float hd2 = h[2] > 0.f ? h[2] : expm1f(h[2]);
        float hd3 = h[3] > 0.f ? h[3] : expm1f(h[3]);
        pr = hd0 * wfv.x + hd1 * wfv.y + hd2 * wfv.z + hd3 * wfv.w;
    }
#pragma unroll
    for (int o = 8; o > 0; o >>= 1)
        pr += __shfl_down_sync(0xffffffffu, pr, o, 16);
    if (c == 0) {
        float y = pr + vredS;
        float w = fabsf(y);
        if (w_out) w_out[b * NAG + i] = w;
        qpart[i] = w * agent_qs[b * NAG + i];
    }
    __syncthreads();
    if (tid == 0 && q_out) {
        float q = 0.f;
#pragma unroll
        for (int ii = 0; ii < NAG; ii++) q += qpart[ii];
        q_out[b] = q;
    }
}

// ======================================================================
// launch
// ======================================================================
extern "C" void kernel_launch(void* const* d_in, const int* in_sizes, int n_in,
                              void* d_out, int out_size)
{
    const float* states    = (const float*)d_in[0];
    const float* actions   = (const float*)d_in[1];
    const float* agent_qs  = (const float*)d_in[2];
    const int*   gc        = (const int*)  d_in[4];
    const float* W1a = (const float*)d_in[5];
    const float* b1a = (const float*)d_in[6];
    const float* W1b = (const float*)d_in[7];
    const float* b1b = (const float*)d_in[8];
    const float* Wb  = (const float*)d_in[9];
    const float* bb  = (const float*)d_in[10];
    const float* Wfa = (const float*)d_in[11];
    const float* bfa = (const float*)d_in[12];
    const float* Wfb = (const float*)d_in[13];
    const float* bfb = (const float*)d_in[14];
    const float* Wv1 = (const float*)d_in[15];
    const float* bv1 = (const float*)d_in[16];
    const float* Wv2 = (const float*)d_in[17];
    const float* bv2 = (const float*)d_in[18];

    static bool inited = false;
    if (!inited) {
        cudaFuncSetAttribute(stage1_kernel, cudaFuncAttributeMaxDynamicSharedMemorySize, SMEM_S1);
        cudaFuncSetAttribute(stage2_kernel, cudaFuncAttributeMaxDynamicSharedMemorySize, SMEM_S2);
        inited = true;
    }

    float* out = (float*)d_out;
    float* q_out = nullptr;
    float* w_out = nullptr;
    if (out_size == BATCH + BATCH * NAG)      { q_out = out; w_out = out + BATCH; }
    else if (out_size == BATCH * NAG)         { w_out = out; }
    else if (out_size == BATCH)               { q_out = out; }
    else                                      { q_out = out; w_out = out + BATCH; }

    stage1_kernel<<<S1_TOTAL, 256, SMEM_S1>>>(states, W1a, b1a, Wfa, bfa,
                                              Wb, bb, Wv1, bv1, W1b, actions, gc);
    stage2_kernel<<<128 + 640, 256, SMEM_S2>>>(b1b, Wfb, bfb);
    final_kernel<<<BATCH, 256>>>(actions, Wv2, bv2, agent_qs, q_out, w_out);
}

// round 10
// speedup vs baseline: 1.0739x; 1.0739x over previous
#include <cuda_runtime.h>
#include <cuda_bf16.h>
#include <math.h>
#include <stdint.h>

// Problem constants
#define BATCH 2048      // B*T
#define NAG   16
#define NACT  20
#define DDIM  128
#define NSAMP 32
#define EDIM  64
#define HDIM  256
#define W1N   2560      // E*2*A
#define CATN  640       // 256(h1a)+256(hf)+64(b1)+64(vh)

// ---------------- scratch (device globals) ----------------
__device__ float g_out0[BATCH * CATN];
__device__ __nv_bfloat16 g_Ahi[BATCH * HDIM];
__device__ __nv_bfloat16 g_Alo[BATCH * HDIM];
__device__ __nv_bfloat16 g_Bhi[W1N * HDIM];
__device__ __nv_bfloat16 g_Blo[W1N * HDIM];
__device__ float g_w1 [BATCH * W1N];
__device__ float g_wf [BATCH * EDIM];
__device__ float g_coal[BATCH * NAG * NACT];

// ===================== PTX helpers =====================
__device__ __forceinline__ uint32_t smem_to_u32(const void* p) {
    uint32_t a;
    asm("{ .reg .u64 t; cvta.to.shared.u64 t, %1; cvt.u32.u64 %0, t; }" : "=r"(a) : "l"(p));
    return a;
}
#define LDMATRIX_X4(r, a) \
    asm volatile("ldmatrix.sync.aligned.m8n8.x4.shared.b16 {%0,%1,%2,%3}, [%4];" \
        : "=r"((r)[0]), "=r"((r)[1]), "=r"((r)[2]), "=r"((r)[3]) : "r"(a))
#define MMA16816(c, a, b0, b1) \
    asm volatile("mma.sync.aligned.m16n8k16.row.col.f32.bf16.bf16.f32 " \
        "{%0,%1,%2,%3},{%4,%5,%6,%7},{%8,%9},{%0,%1,%2,%3};" \
        : "+f"((c)[0]), "+f"((c)[1]), "+f"((c)[2]), "+f"((c)[3]) \
        : "r"((a)[0]), "r"((a)[1]), "r"((a)[2]), "r"((a)[3]), "r"(b0), "r"(b1))
#define CP_ASYNC16(dst, src) \
    asm volatile("cp.async.cg.shared.global [%0], [%1], 16;" :: "r"(dst), "l"(src))
#define CP_COMMIT() asm volatile("cp.async.commit_group;" ::: "memory")
#define CP_WAIT1()  asm volatile("cp.async.wait_group 1;" ::: "memory")
#define CP_WAIT0()  asm volatile("cp.async.wait_group 0;" ::: "memory")

// ======================================================================
// STAGE 1: gemm0 (320) + trans_split (640), 66 KB dynamic smem
// ======================================================================
#define S1_GEMM0_BLKS 320
#define S1_TRANS_BLKS 640
#define S1_TOTAL (S1_GEMM0_BLKS + S1_TRANS_BLKS)
#define SMEM_S1  66560   // As 64x132 (33792 B) + Bs 128x64 (32768 B)

__device__ __forceinline__ void gemm0_block(
    int bx, char* smraw, const float* __restrict__ states,
    const float* __restrict__ W1a, const float* __restrict__ b1a,
    const float* __restrict__ Wfa, const float* __restrict__ bfa,
    const float* __restrict__ Wb,  const float* __restrict__ bb,
    const float* __restrict__ Wv1, const float* __restrict__ bv1)
{
    float* As = (float*)smraw;                   // [64][132] (m,k)
    float* Bs = (float*)(smraw + 33792);         // [128][64] (k,n)

    const int tid = threadIdx.x;
    const int n0 = (bx % 10) * 64;
    const int m0 = (bx / 10) * 64;
    const int tx = tid & 15, ty = tid >> 4;

    const float* Bsrc; const float* bias; int ldb; int nc0;
    if      (n0 < 256) { Bsrc = W1a; bias = b1a; ldb = 256; nc0 = n0; }
    else if (n0 < 512) { Bsrc = Wfa; bias = bfa; ldb = 256; nc0 = n0 - 256; }
    else if (n0 < 576) { Bsrc = Wb;  bias = bb;  ldb = 64;  nc0 = 0; }
    else               { Bsrc = Wv1; bias = bv1; ldb = 64;  nc0 = 0; }

#pragma unroll
    for (int j = 0; j < 8; j++) {
        int idx = tid + j * 256;
        int k = idx >> 4, c = idx & 15;
        CP_ASYNC16(smem_to_u32(&Bs[k * 64 + c * 4]),
                   Bsrc + (size_t)k * ldb + nc0 + c * 4);
    }
    CP_COMMIT();

#pragma unroll
    for (int j = 0; j < 8; j++) {
        int idx = tid + j * 256;
        int kg = idx & 31, m = idx >> 5;
        float4 v = *(const float4*)(states + (size_t)(m0 + m) * DDIM + kg * 4);
        *(float4*)&As[m * 132 + kg * 4] = v;
    }
    CP_WAIT0();
    __syncthreads();

    float acc[4][4];
#pragma unroll
    for (int r = 0; r < 4; r++)
#pragma unroll
        for (int j = 0; j < 4; j++) acc[r][j] = 0.f;

#pragma unroll 8
    for (int kk = 0; kk < 128; kk++) {
        float av[4];
#pragma unroll
        for (int r = 0; r < 4; r++) av[r] = As[(ty * 4 + r) * 132 + kk];
        float4 bv = *(const float4*)&Bs[kk * 64 + tx * 4];
        float bw[4] = {bv.x, bv.y, bv.z, bv.w};
#pragma unroll
        for (int r = 0; r < 4; r++)
#pragma unroll
            for (int j = 0; j < 4; j++)
                acc[r][j] += av[r] * bw[j];
    }

    const bool do_relu = (n0 != 512);
    float bs[4];
#pragma unroll
    for (int j = 0; j < 4; j++) bs[j] = bias[nc0 + tx * 4 + j];

#pragma unroll
    for (int r = 0; r < 4; r++) {
        int m = m0 + ty * 4 + r;
        float4 o;
        float* po = &o.x;
#pragma unroll
        for (int j = 0; j < 4; j++) {
            float v = acc[r][j] + bs[j];
            if (do_relu) v = fmaxf(v, 0.f);
            po[j] = v;
        }
        *(float4*)&g_out0[(size_t)m * CATN + n0 + tx * 4] = o;
        if (n0 < 256) {
            __nv_bfloat16 h[4]; float lo[4];
#pragma unroll
            for (int j = 0; j < 4; j++) {
                h[j] = __float2bfloat16(po[j]);
                lo[j] = po[j] - __bfloat162float(h[j]);
            }
            size_t base = (size_t)m * HDIM + n0 + tx * 4;
            *(__nv_bfloat162*)&g_Ahi[base]     = __nv_bfloat162(h[0], h[1]);
            *(__nv_bfloat162*)&g_Ahi[base + 2] = __nv_bfloat162(h[2], h[3]);
            *(__nv_bfloat162*)&g_Alo[base]     = __nv_bfloat162(__float2bfloat16(lo[0]), __float2bfloat16(lo[1]));
            *(__nv_bfloat162*)&g_Alo[base + 2] = __nv_bfloat162(__float2bfloat16(lo[2]), __float2bfloat16(lo[3]));
        }
    }
}

__device__ __forceinline__ void trans_block(int t, char* smraw, const float* __restrict__ W1b)
{
    float* ts = (float*)smraw;      // [32][33]
    int n0 = (t % 80) * 32, k0 = (t / 80) * 32;
    int tx = threadIdx.x & 31, ty = threadIdx.x >> 5;
#pragma unroll
    for (int r = 0; r < 4; r++)
        ts[(ty * 4 + r) * 33 + tx] = W1b[(size_t)(k0 + ty * 4 + r) * W1N + n0 + tx];
    __syncthreads();
#pragma unroll
    for (int r = 0; r < 4; r++) {
        int n = n0 + ty * 4 + r, k = k0 + tx;
        float v = ts[tx * 33 + ty * 4 + r];
        __nv_bfloat16 hi = __float2bfloat16(v);
        float lof = v - __bfloat162float(hi);
        g_Bhi[(size_t)n * HDIM + k] = hi;
        g_Blo[(size_t)n * HDIM + k] = __float2bfloat16(lof);
    }
}

__global__ void __launch_bounds__(256)
stage1_kernel(const float* __restrict__ states,
              const float* __restrict__ W1a, const float* __restrict__ b1a,
              const float* __restrict__ Wfa, const float* __restrict__ bfa,
              const float* __restrict__ Wb,  const float* __restrict__ bb,
              const float* __restrict__ Wv1, const float* __restrict__ bv1,
              const float* __restrict__ W1b)
{
    extern __shared__ __align__(16) char smd[];
    const int bx = blockIdx.x;
    if (bx < S1_GEMM0_BLKS)
        gemm0_block(bx, smd, states, W1a, b1a, Wfa, bfa, Wb, bb, Wv1, bv1);
    else
        trans_block(bx - S1_GEMM0_BLKS, smd, W1b);
}

// ======================================================================
// coal standalone: small static smem -> high occupancy tail-filler
// ======================================================================
__global__ void __launch_bounds__(256)
coal_kernel(const float* __restrict__ actions, const int* __restrict__ gc)
{
    __shared__ int   gcs[NSAMP * NAG];       // 2 KB
    __shared__ int   inv[NSAMP * NAG];       // 2 KB
    __shared__ float act_s[NAG * NACT];      // 1.25 KB
    __shared__ float Ws[NAG * NAG];          // 1 KB

    const int b = blockIdx.x;
    const int tid = threadIdx.x;

    for (int idx = tid; idx < 512; idx += 256)
        gcs[idx] = gc[b * 512 + idx];
    for (int idx = tid; idx < 320; idx += 256)
        act_s[idx] = actions[b * 320 + idx];
    __syncthreads();

    {
        int s = tid >> 4, pos = tid & 15;
        inv[s * 16 + gcs[s * 16 + pos]] = pos;
        inv[(s + 16) * 16 + gcs[(s + 16) * 16 + pos]] = pos;
    }
    __syncthreads();

    {
        int i = tid >> 4, m = tid & 15;
        int w = 0;
#pragma unroll
        for (int s = 0; s < 32; s++) {
            int gi = gcs[s * 16 + i];
            int pm = inv[s * 16 + m];
            w += (pm < gi) ? gi : 0;
        }
        Ws[i * 16 + m] = (float)w;
    }
    __syncthreads();

    {
        int i = tid >> 4, c = tid & 15;
        for (int a = c; a < NACT; a += 16) {
            float sum = 0.f;
#pragma unroll
            for (int m = 0; m < 16; m++)
                sum += Ws[i * 16 + m] * act_s[m * NACT + a];
            g_coal[b * 320 + i * NACT + a] = sum * (1.f / 512.f);
        }
    }
}

// ======================================================================
// STAGE 2: wf (128, first) + hmma 128x128 (320 blocks)
// ======================================================================
#define T_ROWB   80
#define T_BYTES  (128 * T_ROWB)
#define STAGE_B  (4 * T_BYTES)
#define SMEM_S2  (2 * STAGE_B)    // 81920

__device__ __forceinline__ void hmma_block(int bx, char* sm, const float* __restrict__ b1b)
{
    const int tid = threadIdx.x;
    const int wid = tid >> 5, lane = tid & 31;
    const int n0 = (bx % 20) * 128;
    const int m0 = (bx / 20) * 128;
    const int wm = (wid >> 2) * 64;
    const int wn = (wid & 3) * 32;

    float acc[4][4][4];
#pragma unroll
    for (int r = 0; r < 4; r++)
#pragma unroll
        for (int g = 0; g < 4; g++)
#pragma unroll
            for (int c = 0; c < 4; c++) acc[r][g][c] = 0.f;

    const __nv_bfloat16* srcs[4] = {g_Ahi, g_Alo, g_Bhi, g_Blo};

    auto load_stage = [&](int s, int k0) {
#pragma unroll
        for (int t = 0; t < 4; t++) {
            const int r0 = (t < 2) ? m0 : n0;
            const __nv_bfloat16* src = srcs[t];
            char* dstb = sm + s * STAGE_B + t * T_BYTES;
#pragma unroll
            for (int j = 0; j < 2; j++) {
                int idx = tid + j * 256;
                int row = idx >> 2, c = idx & 3;
                CP_ASYNC16(smem_to_u32(dstb + row * T_ROWB + c * 16),
                           (const char*)(src + (size_t)(r0 + row) * HDIM + k0) + c * 16);
            }
        }
    };

    load_stage(0, 0);
    CP_COMMIT();

    for (int kc = 0; kc < 8; kc++) {
        if (kc < 7) { load_stage((kc + 1) & 1, (kc + 1) * 32); CP_COMMIT(); CP_WAIT1(); }
        else        { CP_WAIT0(); }
        __syncthreads();

        char* Ah = sm + (kc & 1) * STAGE_B;
        char* Al = Ah + T_BYTES;
        char* Bh = Ah + 2 * T_BYTES;
        char* Bl = Ah + 3 * T_BYTES;

#pragma unroll
        for (int ks = 0; ks < 2; ks++) {
            const int kb = ks * 32;
            uint32_t ah[4][4], al[4][4], bh[2][4], bl[2][4];
            const int arow = wm + (lane & 15);
            const int akb  = kb + (lane >> 4) * 16;
#pragma unroll
            for (int r = 0; r < 4; r++) {
                LDMATRIX_X4(ah[r], smem_to_u32(Ah + (arow + r * 16) * T_ROWB + akb));
                LDMATRIX_X4(al[r], smem_to_u32(Al + (arow + r * 16) * T_ROWB + akb));
            }
            const int brow = wn + (lane & 7) + (lane >> 4) * 8;
            const int bkb  = kb + ((lane >> 3) & 1) * 16;
#pragma unroll
            for (int g = 0; g < 2; g++) {
                LDMATRIX_X4(bh[g], smem_to_u32(Bh + (brow + g * 16) * T_ROWB + bkb));
                LDMATRIX_X4(bl[g], smem_to_u32(Bl + (brow + g * 16) * T_ROWB + bkb));
            }
#pragma unroll
            for (int r = 0; r < 4; r++)
#pragma unroll
                for (int g = 0; g < 4; g++) {
                    uint32_t b0h = bh[g >> 1][(g & 1) * 2], b1h = bh[g >> 1][(g & 1) * 2 + 1];
                    uint32_t b0l = bl[g >> 1][(g & 1) * 2], b1l = bl[g >> 1][(g & 1) * 2 + 1];
                    MMA16816(acc[r][g], ah[r], b0h, b1h);
                    MMA16816(acc[r][g], ah[r], b0l, b1l);
                    MMA16816(acc[r][g], al[r], b0h, b1h);
                }
        }
        __syncthreads();
    }

    const int mrow  = m0 + wm + (lane >> 2);
    const int ncol0 = n0 + wn + (lane & 3) * 2;
#pragma unroll
    for (int g = 0; g < 4; g++) {
        const int n = ncol0 + g * 8;
        float2 bias = *(const float2*)&b1b[n];
#pragma unroll
        for (int r = 0; r < 4; r++) {
            const int m = mrow + r * 16;
            float2 o0, o1;
            o0.x = fabsf(acc[r][g][0] + bias.x);
            o0.y = fabsf(acc[r][g][1] + bias.y);
            o1.x = fabsf(acc[r][g][2] + bias.x);
            o1.y = fabsf(acc[r][g][3] + bias.y);
            *(float2*)&g_w1[(size_t)m * W1N + n]       = o0;
            *(float2*)&g_w1[(size_t)(m + 8) * W1N + n] = o1;
        }
    }
}

__device__ __forceinline__ void wf_block(int wb, char* sm,
    const float* __restrict__ Wfb, const float* __restrict__ bfb)
{
    float* As = (float*)sm;             // [2][16][36]
    float* Bs = (float*)(sm + 4608);    // [2][32][64]
    const int tid = threadIdx.x;
    const int m0 = wb * 16;
    const int tx = tid & 15, ty = tid >> 4;

    auto load_stage = [&](int s, int k0) {
        if (tid < 128) {
            int row = tid >> 3, c = tid & 7;
            CP_ASYNC16(smem_to_u32(&As[s * 576 + row * 36 + c * 4]),
                       g_out0 + (size_t)(m0 + row) * CATN + 256 + k0 + c * 4);
        }
#pragma unroll
        for (int j = 0; j < 2; j++) {
            int idx = tid * 2 + j;
            int k = idx >> 4, c = idx & 15;
            CP_ASYNC16(smem_to_u32(&Bs[s * 2048 + k * 64 + c * 4]),
                       Wfb + (size_t)(k0 + k) * EDIM + c * 4);
        }
    };

    float acc[4] = {0.f, 0.f, 0.f, 0.f};
    load_stage(0, 0);
    CP_COMMIT();

    for (int c = 0; c < 8; c++) {
        if (c < 7) { load_stage((c + 1) & 1, (c + 1) * 32); CP_COMMIT(); CP_WAIT1(); }
        else       { CP_WAIT0(); }
        __syncthreads();
        const int buf = c & 1;
#pragma unroll
        for (int kk = 0; kk < 32; kk++) {
            float a = As[buf * 576 + ty * 36 + kk];
            float4 bv = *(const float4*)&Bs[buf * 2048 + kk * 64 + tx * 4];
            acc[0] += a * bv.x; acc[1] += a * bv.y;
            acc[2] += a * bv.z; acc[3] += a * bv.w;
        }
        __syncthreads();
    }

    float4 bsv = *(const float4*)&bfb[tx * 4];
    float4 o;
    o.x = fabsf(acc[0] + bsv.x);
    o.y = fabsf(acc[1] + bsv.y);
    o.z = fabsf(acc[2] + bsv.z);
    o.w = fabsf(acc[3] + bsv.w);
    *(float4*)&g_wf[(size_t)(m0 + ty) * EDIM + tx * 4] = o;
}

__global__ void __launch_bounds__(256)
stage2_kernel(const float* __restrict__ b1b,
              const float* __restrict__ Wfb, const float* __restrict__ bfb)
{
    extern __shared__ char sm[];
    const int bx = blockIdx.x;
    if (bx < 128) wf_block(bx, sm, Wfb, bfb);
    else          hmma_block(bx - 128, sm, b1b);
}

// ======================================================================
// STAGE 3: lean final mix (v fused), 256 threads
// ======================================================================
__global__ void __launch_bounds__(256)
final_kernel(const float* __restrict__ actions, const float* __restrict__ Wv2,
             const float* __restrict__ bv2, const float* __restrict__ agent_qs,
             float* __restrict__ q_out, float* __restrict__ w_out)
{
    const int b = blockIdx.x;
    const int tid = threadIdx.x;
    const int i = tid >> 4, c = tid & 15;

    __shared__ float w1s[W1N];
    __shared__ float ins[NAG][40];
    __shared__ float wfs[EDIM], b1s[EDIM];
    __shared__ float vtmp[EDIM];
    __shared__ float vredS;
    __shared__ float qpart[NAG];

    for (int idx = tid; idx < 640; idx += 256)
        ((float4*)w1s)[idx] = ((const float4*)(g_w1 + (size_t)b * W1N))[idx];
    for (int idx = tid; idx < 320; idx += 256) {
        ins[idx / NACT][idx % NACT]        = g_coal[b * 320 + idx];
        ins[idx / NACT][NACT + idx % NACT] = actions[b * 320 + idx];
    }
    if (tid < 64) {
        wfs[tid]  = g_wf[(size_t)b * EDIM + tid];
        b1s[tid]  = g_out0[(size_t)b * CATN + 512 + tid];
        vtmp[tid] = g_out0[(size_t)b * CATN + 576 + tid] * Wv2[tid];
    }
    __syncthreads();

    if (tid < 32) {
        float pv = vtmp[tid] + vtmp[tid + 32];
#pragma unroll
        for (int o = 16; o > 0; o >>= 1)
            pv += __shfl_down_sync(0xffffffffu, pv, o);
        if (tid == 0) vredS = pv + bv2[0];
    }
    __syncthreads();

    const int e0 = c * 4;
    float4 hb = *(const float4*)&b1s[e0];
    float h[4] = {hb.x, hb.y, hb.z, hb.w};
#pragma unroll
    for (int k = 0; k < 40; k++) {
        float a_ = ins[i][k];
        float4 w = *(const float4*)&w1s[k * EDIM + e0];
        h[0] += a_ * w.x; h[1] += a_ * w.y;
        h[2] += a_ * w.z; h[3] += a_ * w.w;
    }
    float4 wfv = *(const float4*)&wfs[e0];
    float pr;
    {
        float hd0 = h[0] > 0.f ? h[0] : expm1f(h[0]);
        float hd1 = h[1] > 0.f ? h[1] : expm1f(h[1]);
        float hd2 = h[2] > 0.f ? h[2] : expm1f(h[2]);
        float hd3 = h[3] > 0.f ? h[3] : expm1f(h[3]);
        pr = hd0 * wfv.x + hd1 * wfv.y + hd2 * wfv.z + hd3 * wfv.w;
    }
#pragma unroll
    for (int o = 8; o > 0; o >>= 1)
        pr += __shfl_down_sync(0xffffffffu, pr, o, 16);
    if (c == 0) {
        float y = pr + vredS;
        float w = fabsf(y);
        if (w_out) w_out[b * NAG + i] = w;
        qpart[i] = w * agent_qs[b * NAG + i];
    }
    __syncthreads();
    if (tid == 0 && q_out) {
        float q = 0.f;
#pragma unroll
        for (int ii = 0; ii < NAG; ii++) q += qpart[ii];
        q_out[b] = q;
    }
}

// ======================================================================
// launch
// ======================================================================
extern "C" void kernel_launch(void* const* d_in, const int* in_sizes, int n_in,
                              void* d_out, int out_size)
{
    const float* states    = (const float*)d_in[0];
    const float* actions   = (const float*)d_in[1];
    const float* agent_qs  = (const float*)d_in[2];
    const int*   gc        = (const int*)  d_in[4];
    const float* W1a = (const float*)d_in[5];
    const float* b1a = (const float*)d_in[6];
    const float* W1b = (const float*)d_in[7];
    const float* b1b = (const float*)d_in[8];
    const float* Wb  = (const float*)d_in[9];
    const float* bb  = (const float*)d_in[10];
    const float* Wfa = (const float*)d_in[11];
    const float* bfa = (const float*)d_in[12];
    const float* Wfb = (const float*)d_in[13];
    const float* bfb = (const float*)d_in[14];
    const float* Wv1 = (const float*)d_in[15];
    const float* bv1 = (const float*)d_in[16];
    const float* Wv2 = (const float*)d_in[17];
    const float* bv2 = (const float*)d_in[18];

    static bool inited = false;
    if (!inited) {
        cudaFuncSetAttribute(stage1_kernel, cudaFuncAttributeMaxDynamicSharedMemorySize, SMEM_S1);
        cudaFuncSetAttribute(stage2_kernel, cudaFuncAttributeMaxDynamicSharedMemorySize, SMEM_S2);
        inited = true;
    }

    float* out = (float*)d_out;
    float* q_out = nullptr;
    float* w_out = nullptr;
    if (out_size == BATCH + BATCH * NAG)      { q_out = out; w_out = out + BATCH; }
    else if (out_size == BATCH * NAG)         { w_out = out; }
    else if (out_size == BATCH)               { q_out = out; }
    else                                      { q_out = out; w_out = out + BATCH; }

    stage1_kernel<<<S1_TOTAL, 256, SMEM_S1>>>(states, W1a, b1a, Wfa, bfa,
                                              Wb, bb, Wv1, bv1, W1b);
    coal_kernel<<<BATCH, 256>>>(actions, gc);
    stage2_kernel<<<128 + 320, 256, SMEM_S2>>>(b1b, Wfb, bfb);
    final_kernel<<<BATCH, 256>>>(actions, Wv2, bv2, agent_qs, q_out, w_out);
}

// round 11
// speedup vs baseline: 1.1322x; 1.0543x over previous
#include <cuda_runtime.h>
#include <cuda_bf16.h>
#include <math.h>
#include <stdint.h>

// Problem constants
#define BATCH 2048      // B*T
#define NAG   16
#define NACT  20
#define DDIM  128
#define NSAMP 32
#define EDIM  64
#define HDIM  256
#define W1N   2560      // E*2*A
#define CATN  640       // 256(h1a)+256(hf)+64(b1)+64(vh)

// ---------------- scratch (device globals) ----------------
__device__ float g_out0[BATCH * CATN];
__device__ __nv_bfloat16 g_Ahi[BATCH * HDIM];
__device__ __nv_bfloat16 g_Alo[BATCH * HDIM];
__device__ __nv_bfloat16 g_Bhi[W1N * HDIM];
__device__ __nv_bfloat16 g_Blo[W1N * HDIM];
__device__ float g_w1 [BATCH * W1N];
__device__ float g_wf [BATCH * EDIM];
__device__ float g_coal[BATCH * NAG * NACT];

// ===================== PTX helpers =====================
__device__ __forceinline__ uint32_t smem_to_u32(const void* p) {
    uint32_t a;
    asm("{ .reg .u64 t; cvta.to.shared.u64 t, %1; cvt.u32.u64 %0, t; }" : "=r"(a) : "l"(p));
    return a;
}
#define LDMATRIX_X4(r, a) \
    asm volatile("ldmatrix.sync.aligned.m8n8.x4.shared.b16 {%0,%1,%2,%3}, [%4];" \
        : "=r"((r)[0]), "=r"((r)[1]), "=r"((r)[2]), "=r"((r)[3]) : "r"(a))
#define MMA16816(c, a, b0, b1) \
    asm volatile("mma.sync.aligned.m16n8k16.row.col.f32.bf16.bf16.f32 " \
        "{%0,%1,%2,%3},{%4,%5,%6,%7},{%8,%9},{%0,%1,%2,%3};" \
        : "+f"((c)[0]), "+f"((c)[1]), "+f"((c)[2]), "+f"((c)[3]) \
        : "r"((a)[0]), "r"((a)[1]), "r"((a)[2]), "r"((a)[3]), "r"(b0), "r"(b1))
#define CP_ASYNC16(dst, src) \
    asm volatile("cp.async.cg.shared.global [%0], [%1], 16;" :: "r"(dst), "l"(src))
#define CP_COMMIT() asm volatile("cp.async.commit_group;" ::: "memory")
#define CP_WAIT1()  asm volatile("cp.async.wait_group 1;" ::: "memory")
#define CP_WAIT0()  asm volatile("cp.async.wait_group 0;" ::: "memory")

// ======================================================================
// STAGE 1: gemm0 (320) + trans_split (640), 66 KB dynamic smem
// ======================================================================
#define S1_GEMM0_BLKS 320
#define S1_TRANS_BLKS 640
#define S1_TOTAL (S1_GEMM0_BLKS + S1_TRANS_BLKS)
#define SMEM_S1  66560

__device__ __forceinline__ void gemm0_block(
    int bx, char* smraw, const float* __restrict__ states,
    const float* __restrict__ W1a, const float* __restrict__ b1a,
    const float* __restrict__ Wfa, const float* __restrict__ bfa,
    const float* __restrict__ Wb,  const float* __restrict__ bb,
    const float* __restrict__ Wv1, const float* __restrict__ bv1)
{
    float* As = (float*)smraw;                   // [64][132]
    float* Bs = (float*)(smraw + 33792);         // [128][64]

    const int tid = threadIdx.x;
    const int n0 = (bx % 10) * 64;
    const int m0 = (bx / 10) * 64;
    const int tx = tid & 15, ty = tid >> 4;

    const float* Bsrc; const float* bias; int ldb; int nc0;
    if      (n0 < 256) { Bsrc = W1a; bias = b1a; ldb = 256; nc0 = n0; }
    else if (n0 < 512) { Bsrc = Wfa; bias = bfa; ldb = 256; nc0 = n0 - 256; }
    else if (n0 < 576) { Bsrc = Wb;  bias = bb;  ldb = 64;  nc0 = 0; }
    else               { Bsrc = Wv1; bias = bv1; ldb = 64;  nc0 = 0; }

#pragma unroll
    for (int j = 0; j < 8; j++) {
        int idx = tid + j * 256;
        int k = idx >> 4, c = idx & 15;
        CP_ASYNC16(smem_to_u32(&Bs[k * 64 + c * 4]),
                   Bsrc + (size_t)k * ldb + nc0 + c * 4);
    }
    CP_COMMIT();

#pragma unroll
    for (int j = 0; j < 8; j++) {
        int idx = tid + j * 256;
        int kg = idx & 31, m = idx >> 5;
        float4 v = *(const float4*)(states + (size_t)(m0 + m) * DDIM + kg * 4);
        *(float4*)&As[m * 132 + kg * 4] = v;
    }
    CP_WAIT0();
    __syncthreads();

    float acc[4][4];
#pragma unroll
    for (int r = 0; r < 4; r++)
#pragma unroll
        for (int j = 0; j < 4; j++) acc[r][j] = 0.f;

#pragma unroll 8
    for (int kk = 0; kk < 128; kk++) {
        float av[4];
#pragma unroll
        for (int r = 0; r < 4; r++) av[r] = As[(ty * 4 + r) * 132 + kk];
        float4 bv = *(const float4*)&Bs[kk * 64 + tx * 4];
        float bw[4] = {bv.x, bv.y, bv.z, bv.w};
#pragma unroll
        for (int r = 0; r < 4; r++)
#pragma unroll
            for (int j = 0; j < 4; j++)
                acc[r][j] += av[r] * bw[j];
    }

    const bool do_relu = (n0 != 512);
    float bs[4];
#pragma unroll
    for (int j = 0; j < 4; j++) bs[j] = bias[nc0 + tx * 4 + j];

#pragma unroll
    for (int r = 0; r < 4; r++) {
        int m = m0 + ty * 4 + r;
        float4 o;
        float* po = &o.x;
#pragma unroll
        for (int j = 0; j < 4; j++) {
            float v = acc[r][j] + bs[j];
            if (do_relu) v = fmaxf(v, 0.f);
            po[j] = v;
        }
        *(float4*)&g_out0[(size_t)m * CATN + n0 + tx * 4] = o;
        if (n0 < 256) {
            __nv_bfloat16 h[4]; float lo[4];
#pragma unroll
            for (int j = 0; j < 4; j++) {
                h[j] = __float2bfloat16(po[j]);
                lo[j] = po[j] - __bfloat162float(h[j]);
            }
            size_t base = (size_t)m * HDIM + n0 + tx * 4;
            *(__nv_bfloat162*)&g_Ahi[base]     = __nv_bfloat162(h[0], h[1]);
            *(__nv_bfloat162*)&g_Ahi[base + 2] = __nv_bfloat162(h[2], h[3]);
            *(__nv_bfloat162*)&g_Alo[base]     = __nv_bfloat162(__float2bfloat16(lo[0]), __float2bfloat16(lo[1]));
            *(__nv_bfloat162*)&g_Alo[base + 2] = __nv_bfloat162(__float2bfloat16(lo[2]), __float2bfloat16(lo[3]));
        }
    }
}

__device__ __forceinline__ void trans_block(int t, char* smraw, const float* __restrict__ W1b)
{
    float* ts = (float*)smraw;      // [32][33]
    int n0 = (t % 80) * 32, k0 = (t / 80) * 32;
    int tx = threadIdx.x & 31, ty = threadIdx.x >> 5;
#pragma unroll
    for (int r = 0; r < 4; r++)
        ts[(ty * 4 + r) * 33 + tx] = W1b[(size_t)(k0 + ty * 4 + r) * W1N + n0 + tx];
    __syncthreads();
#pragma unroll
    for (int r = 0; r < 4; r++) {
        int n = n0 + ty * 4 + r, k = k0 + tx;
        float v = ts[tx * 33 + ty * 4 + r];
        __nv_bfloat16 hi = __float2bfloat16(v);
        float lof = v - __bfloat162float(hi);
        g_Bhi[(size_t)n * HDIM + k] = hi;
        g_Blo[(size_t)n * HDIM + k] = __float2bfloat16(lof);
    }
}

__global__ void __launch_bounds__(256)
stage1_kernel(const float* __restrict__ states,
              const float* __restrict__ W1a, const float* __restrict__ b1a,
              const float* __restrict__ Wfa, const float* __restrict__ bfa,
              const float* __restrict__ Wb,  const float* __restrict__ bb,
              const float* __restrict__ Wv1, const float* __restrict__ bv1,
              const float* __restrict__ W1b)
{
    extern __shared__ __align__(16) char smd[];
    const int bx = blockIdx.x;
    if (bx < S1_GEMM0_BLKS)
        gemm0_block(bx, smd, states, W1a, b1a, Wfa, bfa, Wb, bb, Wv1, bv1);
    else
        trans_block(bx - S1_GEMM0_BLKS, smd, W1b);
}

// ======================================================================
// coal standalone (small smem, high occupancy)
// ======================================================================
__global__ void __launch_bounds__(256)
coal_kernel(const float* __restrict__ actions, const int* __restrict__ gc)
{
    __shared__ int   gcs[NSAMP * NAG];
    __shared__ int   inv[NSAMP * NAG];
    __shared__ float act_s[NAG * NACT];
    __shared__ float Ws[NAG * NAG];

    const int b = blockIdx.x;
    const int tid = threadIdx.x;

    for (int idx = tid; idx < 512; idx += 256)
        gcs[idx] = gc[b * 512 + idx];
    for (int idx = tid; idx < 320; idx += 256)
        act_s[idx] = actions[b * 320 + idx];
    __syncthreads();

    {
        int s = tid >> 4, pos = tid & 15;
        inv[s * 16 + gcs[s * 16 + pos]] = pos;
        inv[(s + 16) * 16 + gcs[(s + 16) * 16 + pos]] = pos;
    }
    __syncthreads();

    {
        int i = tid >> 4, m = tid & 15;
        int w = 0;
#pragma unroll
        for (int s = 0; s < 32; s++) {
            int gi = gcs[s * 16 + i];
            int pm = inv[s * 16 + m];
            w += (pm < gi) ? gi : 0;
        }
        Ws[i * 16 + m] = (float)w;
    }
    __syncthreads();

    {
        int i = tid >> 4, c = tid & 15;
        for (int a = c; a < NACT; a += 16) {
            float sum = 0.f;
#pragma unroll
            for (int m = 0; m < 16; m++)
                sum += Ws[i * 16 + m] * act_s[m * NACT + a];
            g_coal[b * 320 + i * NACT + a] = sum * (1.f / 512.f);
        }
    }
}

// ======================================================================
// STAGE 2: wf (128, first) + hmma 128x128 (320 blocks)
// ======================================================================
#define T_ROWB   80
#define T_BYTES  (128 * T_ROWB)
#define STAGE_B  (4 * T_BYTES)
#define SMEM_S2  (2 * STAGE_B)    // 81920

__device__ __forceinline__ void hmma_block(int bx, char* sm, const float* __restrict__ b1b)
{
    const int tid = threadIdx.x;
    const int wid = tid >> 5, lane = tid & 31;
    const int n0 = (bx % 20) * 128;
    const int m0 = (bx / 20) * 128;
    const int wm = (wid >> 2) * 64;
    const int wn = (wid & 3) * 32;

    float acc[4][4][4];
#pragma unroll
    for (int r = 0; r < 4; r++)
#pragma unroll
        for (int g = 0; g < 4; g++)
#pragma unroll
            for (int c = 0; c < 4; c++) acc[r][g][c] = 0.f;

    const __nv_bfloat16* srcs[4] = {g_Ahi, g_Alo, g_Bhi, g_Blo};

    auto load_stage = [&](int s, int k0) {
#pragma unroll
        for (int t = 0; t < 4; t++) {
            const int r0 = (t < 2) ? m0 : n0;
            const __nv_bfloat16* src = srcs[t];
            char* dstb = sm + s * STAGE_B + t * T_BYTES;
#pragma unroll
            for (int j = 0; j < 2; j++) {
                int idx = tid + j * 256;
                int row = idx >> 2, c = idx & 3;
                CP_ASYNC16(smem_to_u32(dstb + row * T_ROWB + c * 16),
                           (const char*)(src + (size_t)(r0 + row) * HDIM + k0) + c * 16);
            }
        }
    };

    load_stage(0, 0);
    CP_COMMIT();

    for (int kc = 0; kc < 8; kc++) {
        if (kc < 7) { load_stage((kc + 1) & 1, (kc + 1) * 32); CP_COMMIT(); CP_WAIT1(); }
        else        { CP_WAIT0(); }
        __syncthreads();

        char* Ah = sm + (kc & 1) * STAGE_B;
        char* Al = Ah + T_BYTES;
        char* Bh = Ah + 2 * T_BYTES;
        char* Bl = Ah + 3 * T_BYTES;

#pragma unroll
        for (int ks = 0; ks < 2; ks++) {
            const int kb = ks * 32;
            uint32_t ah[4][4], al[4][4], bh[2][4], bl[2][4];
            const int arow = wm + (lane & 15);
            const int akb  = kb + (lane >> 4) * 16;
#pragma unroll
            for (int r = 0; r < 4; r++) {
                LDMATRIX_X4(ah[r], smem_to_u32(Ah + (arow + r * 16) * T_ROWB + akb));
                LDMATRIX_X4(al[r], smem_to_u32(Al + (arow + r * 16) * T_ROWB + akb));
            }
            const int brow = wn + (lane & 7) + (lane >> 4) * 8;
            const int bkb  = kb + ((lane >> 3) & 1) * 16;
#pragma unroll
            for (int g = 0; g < 2; g++) {
                LDMATRIX_X4(bh[g], smem_to_u32(Bh + (brow + g * 16) * T_ROWB + bkb));
                LDMATRIX_X4(bl[g], smem_to_u32(Bl + (brow + g * 16) * T_ROWB + bkb));
            }
#pragma unroll
            for (int r = 0; r < 4; r++)
#pragma unroll
                for (int g = 0; g < 4; g++) {
                    uint32_t b0h = bh[g >> 1][(g & 1) * 2], b1h = bh[g >> 1][(g & 1) * 2 + 1];
                    uint32_t b0l = bl[g >> 1][(g & 1) * 2], b1l = bl[g >> 1][(g & 1) * 2 + 1];
                    MMA16816(acc[r][g], ah[r], b0h, b1h);
                    MMA16816(acc[r][g], ah[r], b0l, b1l);
                    MMA16816(acc[r][g], al[r], b0h, b1h);
                }
        }
        __syncthreads();
    }

    const int mrow  = m0 + wm + (lane >> 2);
    const int ncol0 = n0 + wn + (lane & 3) * 2;
#pragma unroll
    for (int g = 0; g < 4; g++) {
        const int n = ncol0 + g * 8;
        float2 bias = *(const float2*)&b1b[n];
#pragma unroll
        for (int r = 0; r < 4; r++) {
            const int m = mrow + r * 16;
            float2 o0, o1;
            o0.x = fabsf(acc[r][g][0] + bias.x);
            o0.y = fabsf(acc[r][g][1] + bias.y);
            o1.x = fabsf(acc[r][g][2] + bias.x);
            o1.y = fabsf(acc[r][g][3] + bias.y);
            *(float2*)&g_w1[(size_t)m * W1N + n]       = o0;
            *(float2*)&g_w1[(size_t)(m + 8) * W1N + n] = o1;
        }
    }
}

__device__ __forceinline__ void wf_block(int wb, char* sm,
    const float* __restrict__ Wfb, const float* __restrict__ bfb)
{
    float* As = (float*)sm;             // [2][16][36]
    float* Bs = (float*)(sm + 4608);    // [2][32][64]
    const int tid = threadIdx.x;
    const int m0 = wb * 16;
    const int tx = tid & 15, ty = tid >> 4;

    auto load_stage = [&](int s, int k0) {
        if (tid < 128) {
            int row = tid >> 3, c = tid & 7;
            CP_ASYNC16(smem_to_u32(&As[s * 576 + row * 36 + c * 4]),
                       g_out0 + (size_t)(m0 + row) * CATN + 256 + k0 + c * 4);
        }
#pragma unroll
        for (int j = 0; j < 2; j++) {
            int idx = tid * 2 + j;
            int k = idx >> 4, c = idx & 15;
            CP_ASYNC16(smem_to_u32(&Bs[s * 2048 + k * 64 + c * 4]),
                       Wfb + (size_t)(k0 + k) * EDIM + c * 4);
        }
    };

    float acc[4] = {0.f, 0.f, 0.f, 0.f};
    load_stage(0, 0);
    CP_COMMIT();

    for (int c = 0; c < 8; c++) {
        if (c < 7) { load_stage((c + 1) & 1, (c + 1) * 32); CP_COMMIT(); CP_WAIT1(); }
        else       { CP_WAIT0(); }
        __syncthreads();
        const int buf = c & 1;
#pragma unroll
        for (int kk = 0; kk < 32; kk++) {
            float a = As[buf * 576 + ty * 36 + kk];
            float4 bv = *(const float4*)&Bs[buf * 2048 + kk * 64 + tx * 4];
            acc[0] += a * bv.x; acc[1] += a * bv.y;
            acc[2] += a * bv.z; acc[3] += a * bv.w;
        }
        __syncthreads();
    }

    float4 bsv = *(const float4*)&bfb[tx * 4];
    float4 o;
    o.x = fabsf(acc[0] + bsv.x);
    o.y = fabsf(acc[1] + bsv.y);
    o.z = fabsf(acc[2] + bsv.z);
    o.w = fabsf(acc[3] + bsv.w);
    *(float4*)&g_wf[(size_t)(m0 + ty) * EDIM + tx * 4] = o;
}

__global__ void __launch_bounds__(256)
stage2_kernel(const float* __restrict__ b1b,
              const float* __restrict__ Wfb, const float* __restrict__ bfb)
{
    extern __shared__ char sm[];
    const int bx = blockIdx.x;
    if (bx < 128) wf_block(bx, sm, Wfb, bfb);
    else          hmma_block(bx - 128, sm, b1b);
}

// ======================================================================
// STAGE 3: final mix, register-tiled (4i x 4e per thread), 16 rows/block
// ======================================================================
// smem float offsets
#define FS_W1    0        // [2][4][2560]  (two cp.async buffers of 4 rows)
#define FS_INST  20480    // [4][40][16]
#define FS_B1    23040    // [4][64]
#define FS_WF    23296    // [4][64]
#define FS_VP    23552    // [4][2] (padded)
#define FS_YROW  23584    // [4][16]
#define FINAL_SMEM ((23584 + 64) * 4)   // 94592 bytes

__global__ void __launch_bounds__(256)
final_kernel(const float* __restrict__ actions, const float* __restrict__ Wv2,
             const float* __restrict__ bv2, const float* __restrict__ agent_qs,
             float* __restrict__ q_out, float* __restrict__ w_out)
{
    extern __shared__ __align__(16) float fs[];
    float* w1c  = fs + FS_W1;
    float* insT = fs + FS_INST;
    float* b1c  = fs + FS_B1;
    float* wfc  = fs + FS_WF;
    float* vpart= fs + FS_VP;
    float* yrow = fs + FS_YROW;

    const int tid = threadIdx.x;
    const int b00 = blockIdx.x * 16;

    auto load_w1 = [&](int c) {
        float* dst = w1c + (c & 1) * 10240;
        const float* src0 = g_w1 + (size_t)(b00 + c * 4) * W1N;
#pragma unroll
        for (int j = 0; j < 10; j++) {
            int idx = tid + j * 256;
            CP_ASYNC16(smem_to_u32(dst + idx * 4), src0 + (size_t)idx * 4);
        }
    };
    load_w1(0);
    CP_COMMIT();

    const int r  = tid >> 6;        // 0..3  (row within chunk)
    const int u  = tid & 63;
    const int ig = u >> 4;          // 0..3
    const int eg = u & 15;          // 0..15
    const int i0 = ig * 4, e0 = eg * 4;

    for (int c = 0; c < 4; c++) {
        // ---- build insT / b1 / wf / vpart for this chunk ----
#pragma unroll
        for (int j = 0; j < 10; j++) {
            int idx = tid + j * 256;          // 0..2559
            int rr = idx / 640, rem = idx % 640;
            int k = rem >> 4, i = rem & 15;
            int bb = b00 + c * 4 + rr;
            float v = (k < 20) ? g_coal[bb * 320 + i * 20 + k]
                               : actions[bb * 320 + i * 20 + (k - 20)];
            insT[rr * 640 + k * 16 + i] = v;
        }
        {
            const int brow = b00 + c * 4 + r;
            int e = u;
            b1c[r * 64 + e] = g_out0[(size_t)brow * CATN + 512 + e];
            wfc[r * 64 + e] = g_wf[(size_t)brow * EDIM + e];
            float pv = g_out0[(size_t)brow * CATN + 576 + e] * Wv2[e];
#pragma unroll
            for (int o = 16; o > 0; o >>= 1)
                pv += __shfl_down_sync(0xffffffffu, pv, o);
            if ((u & 31) == 0) vpart[r * 2 + (u >> 5)] = pv;
        }
        if (c < 3) { load_w1(c + 1); CP_COMMIT(); CP_WAIT1(); }
        else       { CP_WAIT0(); }
        __syncthreads();

        // ---- register-tiled contraction: 4i x 4e per thread ----
        const float* wrow = w1c + (c & 1) * 10240 + r * 2560;
        const float* irow = insT + r * 640;
        float acc[4][4];
#pragma unroll
        for (int ii = 0; ii < 4; ii++)
#pragma unroll
            for (int ee = 0; ee < 4; ee++) acc[ii][ee] = 0.f;

#pragma unroll 8
        for (int k = 0; k < 40; k++) {
            float4 wv = *(const float4*)&wrow[k * 64 + e0];
            float4 iv = *(const float4*)&irow[k * 16 + i0];
            float wa[4] = {wv.x, wv.y, wv.z, wv.w};
            float ia[4] = {iv.x, iv.y, iv.z, iv.w};
#pragma unroll
            for (int ii = 0; ii < 4; ii++)
#pragma unroll
                for (int ee = 0; ee < 4; ee++)
                    acc[ii][ee] += ia[ii] * wa[ee];
        }

        // ---- epilogue: elu + wf-dot + reduce over eg ----
        float4 bv = *(const float4*)&b1c[r * 64 + e0];
        float4 wfv = *(const float4*)&wfc[r * 64 + e0];
        float ba[4] = {bv.x, bv.y, bv.z, bv.w};
        float wa[4] = {wfv.x, wfv.y, wfv.z, wfv.w};
        float p[4];
#pragma unroll
        for (int ii = 0; ii < 4; ii++) {
            float s = 0.f;
#pragma unroll
            for (int ee = 0; ee < 4; ee++) {
                float h = acc[ii][ee] + ba[ee];
                float hd = h > 0.f ? h : expm1f(h);
                s += hd * wa[ee];
            }
            p[ii] = s;
        }
#pragma unroll
        for (int o = 8; o > 0; o >>= 1)
#pragma unroll
            for (int ii = 0; ii < 4; ii++)
                p[ii] += __shfl_down_sync(0xffffffffu, p[ii], o, 16);
        if (eg == 0) {
#pragma unroll
            for (int ii = 0; ii < 4; ii++)
                yrow[r * 16 + i0 + ii] = p[ii];
        }
        __syncthreads();

        // ---- outputs for this chunk ----
        if (tid < 64) {
            int rr = tid >> 4, i = tid & 15;
            int bb = b00 + c * 4 + rr;
            float y = yrow[rr * 16 + i] + vpart[rr * 2] + vpart[rr * 2 + 1] + bv2[0];
            float w = fabsf(y);
            if (w_out) w_out[bb * 16 + i] = w;
            float qp = w * agent_qs[bb * 16 + i];
#pragma unroll
            for (int o = 8; o > 0; o >>= 1)
                qp += __shfl_down_sync(0xffffffffu, qp, o, 16);
            if (i == 0 && q_out) q_out[bb] = qp;
        }
        __syncthreads();   // before insT/b1c/wfc overwrite next chunk
    }
}

// ======================================================================
// launch
// ======================================================================
extern "C" void kernel_launch(void* const* d_in, const int* in_sizes, int n_in,
                              void* d_out, int out_size)
{
    const float* states    = (const float*)d_in[0];
    const float* actions   = (const float*)d_in[1];
    const float* agent_qs  = (const float*)d_in[2];
    const int*   gc        = (const int*)  d_in[4];
    const float* W1a = (const float*)d_in[5];
    const float* b1a = (const float*)d_in[6];
    const float* W1b = (const float*)d_in[7];
    const float* b1b = (const float*)d_in[8];
    const float* Wb  = (const float*)d_in[9];
    const float* bb  = (const float*)d_in[10];
    const float* Wfa = (const float*)d_in[11];
    const float* bfa = (const float*)d_in[12];
    const float* Wfb = (const float*)d_in[13];
    const float* bfb = (const float*)d_in[14];
    const float* Wv1 = (const float*)d_in[15];
    const float* bv1 = (const float*)d_in[16];
    const float* Wv2 = (const float*)d_in[17];
    const float* bv2 = (const float*)d_in[18];

    static bool inited = false;
    if (!inited) {
        cudaFuncSetAttribute(stage1_kernel, cudaFuncAttributeMaxDynamicSharedMemorySize, SMEM_S1);
        cudaFuncSetAttribute(stage2_kernel, cudaFuncAttributeMaxDynamicSharedMemorySize, SMEM_S2);
        cudaFuncSetAttribute(final_kernel, cudaFuncAttributeMaxDynamicSharedMemorySize, FINAL_SMEM);
        inited = true;
    }

    float* out = (float*)d_out;
    float* q_out = nullptr;
    float* w_out = nullptr;
    if (out_size == BATCH + BATCH * NAG)      { q_out = out; w_out = out + BATCH; }
    else if (out_size == BATCH * NAG)         { w_out = out; }
    else if (out_size == BATCH)               { q_out = out; }
    else                                      { q_out = out; w_out = out + BATCH; }

    stage1_kernel<<<S1_TOTAL, 256, SMEM_S1>>>(states, W1a, b1a, Wfa, bfa,
                                              Wb, bb, Wv1, bv1, W1b);
    coal_kernel<<<BATCH, 256>>>(actions, gc);
    stage2_kernel<<<128 + 320, 256, SMEM_S2>>>(b1b, Wfb, bfb);
    final_kernel<<<BATCH / 16, 256, FINAL_SMEM>>>(actions, Wv2, bv2, agent_qs,
                                                  q_out, w_out);
}

// round 12
// speedup vs baseline: 1.1726x; 1.0357x over previous
#include <cuda_runtime.h>
#include <cuda_bf16.h>
#include <math.h>
#include <stdint.h>

// Problem constants
#define BATCH 2048      // B*T
#define NAG   16
#define NACT  20
#define DDIM  128
#define NSAMP 32
#define EDIM  64
#define HDIM  256
#define W1N   2560      // E*2*A
#define CATN  640       // 256(h1a)+256(hf)+64(b1)+64(vh)

// ---------------- scratch (device globals) ----------------
__device__ float g_out0[BATCH * CATN];
__device__ __nv_bfloat16 g_Ahi[BATCH * HDIM];
__device__ __nv_bfloat16 g_Alo[BATCH * HDIM];
__device__ __nv_bfloat16 g_Bhi[W1N * HDIM];
__device__ __nv_bfloat16 g_Blo[W1N * HDIM];
__device__ float g_w1 [BATCH * W1N];
__device__ float g_wf [BATCH * EDIM];
__device__ float g_coal[BATCH * NAG * NACT];

// ===================== PTX helpers =====================
__device__ __forceinline__ uint32_t smem_to_u32(const void* p) {
    uint32_t a;
    asm("{ .reg .u64 t; cvta.to.shared.u64 t, %1; cvt.u32.u64 %0, t; }" : "=r"(a) : "l"(p));
    return a;
}
#define LDMATRIX_X4(r, a) \
    asm volatile("ldmatrix.sync.aligned.m8n8.x4.shared.b16 {%0,%1,%2,%3}, [%4];" \
        : "=r"((r)[0]), "=r"((r)[1]), "=r"((r)[2]), "=r"((r)[3]) : "r"(a))
#define MMA16816(c, a, b0, b1) \
    asm volatile("mma.sync.aligned.m16n8k16.row.col.f32.bf16.bf16.f32 " \
        "{%0,%1,%2,%3},{%4,%5,%6,%7},{%8,%9},{%0,%1,%2,%3};" \
        : "+f"((c)[0]), "+f"((c)[1]), "+f"((c)[2]), "+f"((c)[3]) \
        : "r"((a)[0]), "r"((a)[1]), "r"((a)[2]), "r"((a)[3]), "r"(b0), "r"(b1))
#define CP_ASYNC16(dst, src) \
    asm volatile("cp.async.cg.shared.global [%0], [%1], 16;" :: "r"(dst), "l"(src))
#define CP_COMMIT() asm volatile("cp.async.commit_group;" ::: "memory")
#define CP_WAIT1()  asm volatile("cp.async.wait_group 1;" ::: "memory")
#define CP_WAIT0()  asm volatile("cp.async.wait_group 0;" ::: "memory")

// ======================================================================
// STAGE 1: gemm0 (320) + trans_split (640), 66 KB dynamic smem
// ======================================================================
#define S1_GEMM0_BLKS 320
#define S1_TRANS_BLKS 640
#define S1_TOTAL (S1_GEMM0_BLKS + S1_TRANS_BLKS)
#define SMEM_S1  66560

__device__ __forceinline__ void gemm0_block(
    int bx, char* smraw, const float* __restrict__ states,
    const float* __restrict__ W1a, const float* __restrict__ b1a,
    const float* __restrict__ Wfa, const float* __restrict__ bfa,
    const float* __restrict__ Wb,  const float* __restrict__ bb,
    const float* __restrict__ Wv1, const float* __restrict__ bv1)
{
    float* As = (float*)smraw;                   // [64][132]
    float* Bs = (float*)(smraw + 33792);         // [128][64]

    const int tid = threadIdx.x;
    const int n0 = (bx % 10) * 64;
    const int m0 = (bx / 10) * 64;
    const int tx = tid & 15, ty = tid >> 4;

    const float* Bsrc; const float* bias; int ldb; int nc0;
    if      (n0 < 256) { Bsrc = W1a; bias = b1a; ldb = 256; nc0 = n0; }
    else if (n0 < 512) { Bsrc = Wfa; bias = bfa; ldb = 256; nc0 = n0 - 256; }
    else if (n0 < 576) { Bsrc = Wb;  bias = bb;  ldb = 64;  nc0 = 0; }
    else               { Bsrc = Wv1; bias = bv1; ldb = 64;  nc0 = 0; }

#pragma unroll
    for (int j = 0; j < 8; j++) {
        int idx = tid + j * 256;
        int k = idx >> 4, c = idx & 15;
        CP_ASYNC16(smem_to_u32(&Bs[k * 64 + c * 4]),
                   Bsrc + (size_t)k * ldb + nc0 + c * 4);
    }
    CP_COMMIT();

#pragma unroll
    for (int j = 0; j < 8; j++) {
        int idx = tid + j * 256;
        int kg = idx & 31, m = idx >> 5;
        float4 v = *(const float4*)(states + (size_t)(m0 + m) * DDIM + kg * 4);
        *(float4*)&As[m * 132 + kg * 4] = v;
    }
    CP_WAIT0();
    __syncthreads();

    float acc[4][4];
#pragma unroll
    for (int r = 0; r < 4; r++)
#pragma unroll
        for (int j = 0; j < 4; j++) acc[r][j] = 0.f;

#pragma unroll 8
    for (int kk = 0; kk < 128; kk++) {
        float av[4];
#pragma unroll
        for (int r = 0; r < 4; r++) av[r] = As[(ty * 4 + r) * 132 + kk];
        float4 bv = *(const float4*)&Bs[kk * 64 + tx * 4];
        float bw[4] = {bv.x, bv.y, bv.z, bv.w};
#pragma unroll
        for (int r = 0; r < 4; r++)
#pragma unroll
            for (int j = 0; j < 4; j++)
                acc[r][j] += av[r] * bw[j];
    }

    const bool do_relu = (n0 != 512);
    float bs[4];
#pragma unroll
    for (int j = 0; j < 4; j++) bs[j] = bias[nc0 + tx * 4 + j];

#pragma unroll
    for (int r = 0; r < 4; r++) {
        int m = m0 + ty * 4 + r;
        float4 o;
        float* po = &o.x;
#pragma unroll
        for (int j = 0; j < 4; j++) {
            float v = acc[r][j] + bs[j];
            if (do_relu) v = fmaxf(v, 0.f);
            po[j] = v;
        }
        *(float4*)&g_out0[(size_t)m * CATN + n0 + tx * 4] = o;
        if (n0 < 256) {
            __nv_bfloat16 h[4]; float lo[4];
#pragma unroll
            for (int j = 0; j < 4; j++) {
                h[j] = __float2bfloat16(po[j]);
                lo[j] = po[j] - __bfloat162float(h[j]);
            }
            size_t base = (size_t)m * HDIM + n0 + tx * 4;
            *(__nv_bfloat162*)&g_Ahi[base]     = __nv_bfloat162(h[0], h[1]);
            *(__nv_bfloat162*)&g_Ahi[base + 2] = __nv_bfloat162(h[2], h[3]);
            *(__nv_bfloat162*)&g_Alo[base]     = __nv_bfloat162(__float2bfloat16(lo[0]), __float2bfloat16(lo[1]));
            *(__nv_bfloat162*)&g_Alo[base + 2] = __nv_bfloat162(__float2bfloat16(lo[2]), __float2bfloat16(lo[3]));
        }
    }
}

__device__ __forceinline__ void trans_block(int t, char* smraw, const float* __restrict__ W1b)
{
    float* ts = (float*)smraw;      // [32][33]
    int n0 = (t % 80) * 32, k0 = (t / 80) * 32;
    int tx = threadIdx.x & 31, ty = threadIdx.x >> 5;
#pragma unroll
    for (int r = 0; r < 4; r++)
        ts[(ty * 4 + r) * 33 + tx] = W1b[(size_t)(k0 + ty * 4 + r) * W1N + n0 + tx];
    __syncthreads();
#pragma unroll
    for (int r = 0; r < 4; r++) {
        int n = n0 + ty * 4 + r, k = k0 + tx;
        float v = ts[tx * 33 + ty * 4 + r];
        __nv_bfloat16 hi = __float2bfloat16(v);
        float lof = v - __bfloat162float(hi);
        g_Bhi[(size_t)n * HDIM + k] = hi;
        g_Blo[(size_t)n * HDIM + k] = __float2bfloat16(lof);
    }
}

__global__ void __launch_bounds__(256)
stage1_kernel(const float* __restrict__ states,
              const float* __restrict__ W1a, const float* __restrict__ b1a,
              const float* __restrict__ Wfa, const float* __restrict__ bfa,
              const float* __restrict__ Wb,  const float* __restrict__ bb,
              const float* __restrict__ Wv1, const float* __restrict__ bv1,
              const float* __restrict__ W1b)
{
    extern __shared__ __align__(16) char smd[];
    const int bx = blockIdx.x;
    if (bx < S1_GEMM0_BLKS)
        gemm0_block(bx, smd, states, W1a, b1a, Wfa, bfa, Wb, bb, Wv1, bv1);
    else
        trans_block(bx - S1_GEMM0_BLKS, smd, W1b);
}

// ======================================================================
// coal standalone (small smem, high occupancy)
// ======================================================================
__global__ void __launch_bounds__(256)
coal_kernel(const float* __restrict__ actions, const int* __restrict__ gc)
{
    __shared__ int   gcs[NSAMP * NAG];
    __shared__ int   inv[NSAMP * NAG];
    __shared__ float act_s[NAG * NACT];
    __shared__ float Ws[NAG * NAG];

    const int b = blockIdx.x;
    const int tid = threadIdx.x;

    for (int idx = tid; idx < 512; idx += 256)
        gcs[idx] = gc[b * 512 + idx];
    for (int idx = tid; idx < 320; idx += 256)
        act_s[idx] = actions[b * 320 + idx];
    __syncthreads();

    {
        int s = tid >> 4, pos = tid & 15;
        inv[s * 16 + gcs[s * 16 + pos]] = pos;
        inv[(s + 16) * 16 + gcs[(s + 16) * 16 + pos]] = pos;
    }
    __syncthreads();

    {
        int i = tid >> 4, m = tid & 15;
        int w = 0;
#pragma unroll
        for (int s = 0; s < 32; s++) {
            int gi = gcs[s * 16 + i];
            int pm = inv[s * 16 + m];
            w += (pm < gi) ? gi : 0;
        }
        Ws[i * 16 + m] = (float)w;
    }
    __syncthreads();

    {
        int i = tid >> 4, c = tid & 15;
        for (int a = c; a < NACT; a += 16) {
            float sum = 0.f;
#pragma unroll
            for (int m = 0; m < 16; m++)
                sum += Ws[i * 16 + m] * act_s[m * NACT + a];
            g_coal[b * 320 + i * NACT + a] = sum * (1.f / 512.f);
        }
    }
}

// ======================================================================
// STAGE 2: wf (128, first) + hmma 128x128 (320 blocks)
// ======================================================================
#define T_ROWB   80
#define T_BYTES  (128 * T_ROWB)
#define STAGE_B  (4 * T_BYTES)
#define SMEM_S2  (2 * STAGE_B)    // 81920

__device__ __forceinline__ void hmma_block(int bx, char* sm, const float* __restrict__ b1b)
{
    const int tid = threadIdx.x;
    const int wid = tid >> 5, lane = tid & 31;
    const int n0 = (bx % 20) * 128;
    const int m0 = (bx / 20) * 128;
    const int wm = (wid >> 2) * 64;
    const int wn = (wid & 3) * 32;

    float acc[4][4][4];
#pragma unroll
    for (int r = 0; r < 4; r++)
#pragma unroll
        for (int g = 0; g < 4; g++)
#pragma unroll
            for (int c = 0; c < 4; c++) acc[r][g][c] = 0.f;

    const __nv_bfloat16* srcs[4] = {g_Ahi, g_Alo, g_Bhi, g_Blo};

    auto load_stage = [&](int s, int k0) {
#pragma unroll
        for (int t = 0; t < 4; t++) {
            const int r0 = (t < 2) ? m0 : n0;
            const __nv_bfloat16* src = srcs[t];
            char* dstb = sm + s * STAGE_B + t * T_BYTES;
#pragma unroll
            for (int j = 0; j < 2; j++) {
                int idx = tid + j * 256;
                int row = idx >> 2, c = idx & 3;
                CP_ASYNC16(smem_to_u32(dstb + row * T_ROWB + c * 16),
                           (const char*)(src + (size_t)(r0 + row) * HDIM + k0) + c * 16);
            }
        }
    };

    load_stage(0, 0);
    CP_COMMIT();

    for (int kc = 0; kc < 8; kc++) {
        if (kc < 7) { load_stage((kc + 1) & 1, (kc + 1) * 32); CP_COMMIT(); CP_WAIT1(); }
        else        { CP_WAIT0(); }
        __syncthreads();

        char* Ah = sm + (kc & 1) * STAGE_B;
        char* Al = Ah + T_BYTES;
        char* Bh = Ah + 2 * T_BYTES;
        char* Bl = Ah + 3 * T_BYTES;

#pragma unroll
        for (int ks = 0; ks < 2; ks++) {
            const int kb = ks * 32;
            uint32_t ah[4][4], al[4][4], bh[2][4], bl[2][4];
            const int arow = wm + (lane & 15);
            const int akb  = kb + (lane >> 4) * 16;
#pragma unroll
            for (int r = 0; r < 4; r++) {
                LDMATRIX_X4(ah[r], smem_to_u32(Ah + (arow + r * 16) * T_ROWB + akb));
                LDMATRIX_X4(al[r], smem_to_u32(Al + (arow + r * 16) * T_ROWB + akb));
            }
            const int brow = wn + (lane & 7) + (lane >> 4) * 8;
            const int bkb  = kb + ((lane >> 3) & 1) * 16;
#pragma unroll
            for (int g = 0; g < 2; g++) {
                LDMATRIX_X4(bh[g], smem_to_u32(Bh + (brow + g * 16) * T_ROWB + bkb));
                LDMATRIX_X4(bl[g], smem_to_u32(Bl + (brow + g * 16) * T_ROWB + bkb));
            }
#pragma unroll
            for (int r = 0; r < 4; r++)
#pragma unroll
                for (int g = 0; g < 4; g++) {
                    uint32_t b0h = bh[g >> 1][(g & 1) * 2], b1h = bh[g >> 1][(g & 1) * 2 + 1];
                    uint32_t b0l = bl[g >> 1][(g & 1) * 2], b1l = bl[g >> 1][(g & 1) * 2 + 1];
                    MMA16816(acc[r][g], ah[r], b0h, b1h);
                    MMA16816(acc[r][g], ah[r], b0l, b1l);
                    MMA16816(acc[r][g], al[r], b0h, b1h);
                }
        }
        __syncthreads();
    }

    const int mrow  = m0 + wm + (lane >> 2);
    const int ncol0 = n0 + wn + (lane & 3) * 2;
#pragma unroll
    for (int g = 0; g < 4; g++) {
        const int n = ncol0 + g * 8;
        float2 bias = *(const float2*)&b1b[n];
#pragma unroll
        for (int r = 0; r < 4; r++) {
            const int m = mrow + r * 16;
            float2 o0, o1;
            o0.x = fabsf(acc[r][g][0] + bias.x);
            o0.y = fabsf(acc[r][g][1] + bias.y);
            o1.x = fabsf(acc[r][g][2] + bias.x);
            o1.y = fabsf(acc[r][g][3] + bias.y);
            *(float2*)&g_w1[(size_t)m * W1N + n]       = o0;
            *(float2*)&g_w1[(size_t)(m + 8) * W1N + n] = o1;
        }
    }
}

__device__ __forceinline__ void wf_block(int wb, char* sm,
    const float* __restrict__ Wfb, const float* __restrict__ bfb)
{
    float* As = (float*)sm;             // [2][16][36]
    float* Bs = (float*)(sm + 4608);    // [2][32][64]
    const int tid = threadIdx.x;
    const int m0 = wb * 16;
    const int tx = tid & 15, ty = tid >> 4;

    auto load_stage = [&](int s, int k0) {
        if (tid < 128) {
            int row = tid >> 3, c = tid & 7;
            CP_ASYNC16(smem_to_u32(&As[s * 576 + row * 36 + c * 4]),
                       g_out0 + (size_t)(m0 + row) * CATN + 256 + k0 + c * 4);
        }
#pragma unroll
        for (int j = 0; j < 2; j++) {
            int idx = tid * 2 + j;
            int k = idx >> 4, c = idx & 15;
            CP_ASYNC16(smem_to_u32(&Bs[s * 2048 + k * 64 + c * 4]),
                       Wfb + (size_t)(k0 + k) * EDIM + c * 4);
        }
    };

    float acc[4] = {0.f, 0.f, 0.f, 0.f};
    load_stage(0, 0);
    CP_COMMIT();

    for (int c = 0; c < 8; c++) {
        if (c < 7) { load_stage((c + 1) & 1, (c + 1) * 32); CP_COMMIT(); CP_WAIT1(); }
        else       { CP_WAIT0(); }
        __syncthreads();
        const int buf = c & 1;
#pragma unroll
        for (int kk = 0; kk < 32; kk++) {
            float a = As[buf * 576 + ty * 36 + kk];
            float4 bv = *(const float4*)&Bs[buf * 2048 + kk * 64 + tx * 4];
            acc[0] += a * bv.x; acc[1] += a * bv.y;
            acc[2] += a * bv.z; acc[3] += a * bv.w;
        }
        __syncthreads();
    }

    float4 bsv = *(const float4*)&bfb[tx * 4];
    float4 o;
    o.x = fabsf(acc[0] + bsv.x);
    o.y = fabsf(acc[1] + bsv.y);
    o.z = fabsf(acc[2] + bsv.z);
    o.w = fabsf(acc[3] + bsv.w);
    *(float4*)&g_wf[(size_t)(m0 + ty) * EDIM + tx * 4] = o;
}

__global__ void __launch_bounds__(256)
stage2_kernel(const float* __restrict__ b1b,
              const float* __restrict__ Wfb, const float* __restrict__ bfb)
{
    extern __shared__ char sm[];
    const int bx = blockIdx.x;
    if (bx < 128) wf_block(bx, sm, Wfb, bfb);
    else          hmma_block(bx - 128, sm, b1b);
}

// ======================================================================
// STAGE 3: final mix, register-tiled, 4 rows/block, grid 512, one wave
// ======================================================================
// smem float offsets
#define FS_W1    0        // [4][2560]  (single buffer, 40960 B)
#define FS_INST  10240    // [4][40][16]
#define FS_B1    12800    // [4][64]
#define FS_WF    13056    // [4][64]
#define FS_VP    13312    // [4][2]
#define FS_YROW  13328    // [4][16]
#define FINAL_SMEM ((13392 + 16) * 4)   // 53632 bytes

__global__ void __launch_bounds__(256)
final_kernel(const float* __restrict__ actions, const float* __restrict__ Wv2,
             const float* __restrict__ bv2, const float* __restrict__ agent_qs,
             float* __restrict__ q_out, float* __restrict__ w_out)
{
    extern __shared__ __align__(16) float fs[];
    float* w1c  = fs + FS_W1;
    float* insT = fs + FS_INST;
    float* b1c  = fs + FS_B1;
    float* wfc  = fs + FS_WF;
    float* vpart= fs + FS_VP;
    float* yrow = fs + FS_YROW;

    const int tid = threadIdx.x;
    const int b0 = blockIdx.x * 4;

    // w1: 4 rows = 10240 floats = 2560 x 16B, 10 cp.async per thread
    {
        const float* src0 = g_w1 + (size_t)b0 * W1N;
#pragma unroll
        for (int j = 0; j < 10; j++) {
            int idx = tid + j * 256;
            CP_ASYNC16(smem_to_u32(w1c + idx * 4), src0 + (size_t)idx * 4);
        }
        CP_COMMIT();
    }

    const int r  = tid >> 6;        // 0..3  (row)
    const int u  = tid & 63;
    const int ig = u >> 4;          // 0..3
    const int eg = u & 15;          // 0..15
    const int i0 = ig * 4, e0 = eg * 4;

    // ---- build insT / b1 / wf / vpart (overlaps with w1 cp.async) ----
#pragma unroll
    for (int j = 0; j < 10; j++) {
        int idx = tid + j * 256;          // 0..2559
        int rr = idx / 640, rem = idx % 640;
        int k = rem >> 4, i = rem & 15;
        int bb = b0 + rr;
        float v = (k < 20) ? g_coal[bb * 320 + i * 20 + k]
                           : actions[bb * 320 + i * 20 + (k - 20)];
        insT[rr * 640 + k * 16 + i] = v;
    }
    {
        const int brow = b0 + r;
        int e = u;
        b1c[r * 64 + e] = g_out0[(size_t)brow * CATN + 512 + e];
        wfc[r * 64 + e] = g_wf[(size_t)brow * EDIM + e];
        float pv = g_out0[(size_t)brow * CATN + 576 + e] * Wv2[e];
#pragma unroll
        for (int o = 16; o > 0; o >>= 1)
            pv += __shfl_down_sync(0xffffffffu, pv, o);
        if ((u & 31) == 0) vpart[r * 2 + (u >> 5)] = pv;
    }
    CP_WAIT0();
    __syncthreads();

    // ---- register-tiled contraction: 4i x 4e per thread ----
    const float* wrow = w1c + r * 2560;
    const float* irow = insT + r * 640;
    float acc[4][4];
#pragma unroll
    for (int ii = 0; ii < 4; ii++)
#pragma unroll
        for (int ee = 0; ee < 4; ee++) acc[ii][ee] = 0.f;

#pragma unroll 8
    for (int k = 0; k < 40; k++) {
        float4 wv = *(const float4*)&wrow[k * 64 + e0];
        float4 iv = *(const float4*)&irow[k * 16 + i0];
        float wa[4] = {wv.x, wv.y, wv.z, wv.w};
        float ia[4] = {iv.x, iv.y, iv.z, iv.w};
#pragma unroll
        for (int ii = 0; ii < 4; ii++)
#pragma unroll
            for (int ee = 0; ee < 4; ee++)
                acc[ii][ee] += ia[ii] * wa[ee];
    }

    // ---- epilogue: elu + wf-dot + reduce over eg ----
    float4 bv = *(const float4*)&b1c[r * 64 + e0];
    float4 wfv = *(const float4*)&wfc[r * 64 + e0];
    float ba[4] = {bv.x, bv.y, bv.z, bv.w};
    float wa[4] = {wfv.x, wfv.y, wfv.z, wfv.w};
    float p[4];
#pragma unroll
    for (int ii = 0; ii < 4; ii++) {
        float s = 0.f;
#pragma unroll
        for (int ee = 0; ee < 4; ee++) {
            float h = acc[ii][ee] + ba[ee];
            float hd = h > 0.f ? h : expm1f(h);
            s += hd * wa[ee];
        }
        p[ii] = s;
    }
#pragma unroll
    for (int o = 8; o > 0; o >>= 1)
#pragma unroll
        for (int ii = 0; ii < 4; ii++)
            p[ii] += __shfl_down_sync(0xffffffffu, p[ii], o, 16);
    if (eg == 0) {
#pragma unroll
        for (int ii = 0; ii < 4; ii++)
            yrow[r * 16 + i0 + ii] = p[ii];
    }
    __syncthreads();

    // ---- outputs ----
    if (tid < 64) {
        int rr = tid >> 4, i = tid & 15;
        int bb = b0 + rr;
        float y = yrow[rr * 16 + i] + vpart[rr * 2] + vpart[rr * 2 + 1] + bv2[0];
        float w = fabsf(y);
        if (w_out) w_out[bb * 16 + i] = w;
        float qp = w * agent_qs[bb * 16 + i];
#pragma unroll
        for (int o = 8; o > 0; o >>= 1)
            qp += __shfl_down_sync(0xffffffffu, qp, o, 16);
        if (i == 0 && q_out) q_out[bb] = qp;
    }
}

// ======================================================================
// launch
// ======================================================================
extern "C" void kernel_launch(void* const* d_in, const int* in_sizes, int n_in,
                              void* d_out, int out_size)
{
    const float* states    = (const float*)d_in[0];
    const float* actions   = (const float*)d_in[1];
    const float* agent_qs  = (const float*)d_in[2];
    const int*   gc        = (const int*)  d_in[4];
    const float* W1a = (const float*)d_in[5];
    const float* b1a = (const float*)d_in[6];
    const float* W1b = (const float*)d_in[7];
    const float* b1b = (const float*)d_in[8];
    const float* Wb  = (const float*)d_in[9];
    const float* bb  = (const float*)d_in[10];
    const float* Wfa = (const float*)d_in[11];
    const float* bfa = (const float*)d_in[12];
    const float* Wfb = (const float*)d_in[13];
    const float* bfb = (const float*)d_in[14];
    const float* Wv1 = (const float*)d_in[15];
    const float* bv1 = (const float*)d_in[16];
    const float* Wv2 = (const float*)d_in[17];
    const float* bv2 = (const float*)d_in[18];

    static bool inited = false;
    if (!inited) {
        cudaFuncSetAttribute(stage1_kernel, cudaFuncAttributeMaxDynamicSharedMemorySize, SMEM_S1);
        cudaFuncSetAttribute(stage2_kernel, cudaFuncAttributeMaxDynamicSharedMemorySize, SMEM_S2);
        cudaFuncSetAttribute(final_kernel, cudaFuncAttributeMaxDynamicSharedMemorySize, FINAL_SMEM);
        inited = true;
    }

    float* out = (float*)d_out;
    float* q_out = nullptr;
    float* w_out = nullptr;
    if (out_size == BATCH + BATCH * NAG)      { q_out = out; w_out = out + BATCH; }
    else if (out_size == BATCH * NAG)         { w_out = out; }
    else if (out_size == BATCH)               { q_out = out; }
    else                                      { q_out = out; w_out = out + BATCH; }

    stage1_kernel<<<S1_TOTAL, 256, SMEM_S1>>>(states, W1a, b1a, Wfa, bfa,
                                              Wb, bb, Wv1, bv1, W1b);
    coal_kernel<<<BATCH, 256>>>(actions, gc);
    stage2_kernel<<<128 + 320, 256, SMEM_S2>>>(b1b, Wfb, bfb);
    final_kernel<<<BATCH / 4, 256, FINAL_SMEM>>>(actions, Wv2, bv2, agent_qs,
                                                 q_out, w_out);
}